// round 3
// baseline (speedup 1.0000x reference)
#include <cuda_runtime.h>

#define N_K_STEPS 512
#define N_STATE   128
#define N_INPUT   32
#define HIDDEN    256
#define FAN_IN    161   /* 1 + 128 + 32 */

// Tsit5 tableau
__constant__ float c_C[6] = {0.0f, 0.161f, 0.327f, 0.9f, 0.9800255409045097f, 1.0f};
__constant__ float c_A[5][5] = {
  {0.161f, 0.f, 0.f, 0.f, 0.f},
  {-0.008480655492356989f, 0.335480655492357f, 0.f, 0.f, 0.f},
  {2.8971530571054935f, -6.359448489975075f, 4.3622954328695815f, 0.f, 0.f},
  {5.325864828439257f, -11.748883564062828f, 7.4955393428898365f, -0.09249506636175525f, 0.f},
  {5.86145544294642f, -12.92096931784711f, 8.159367898576159f, -0.071584973281401f, -0.028269050394068383f}
};
__constant__ float c_B[6] = {0.09646076681806523f, 0.01f, 0.4798896504144996f,
                             1.379008574103742f, -3.290069515436081f, 2.324710524099774f};

struct SmemLayout {
  float2 w2[128 * 128];     // W2 pairs: [k-pair p][output o] = (W2[o][2p], W2[o][2p+1])  128 KB
  float4 zs4[41];           // z padded to 164 floats ([161..163] = 0)
  float  hs[256];           // hidden activations
  float  partial[8 * 128];  // stage-2 partials: [k-slice][output]
  float  ksh[5][128];       // k1..k5
  float  ustg[6][32];       // interpolated u per stage ([0] unused)
  float  tsh[N_K_STEPS];    // ts cached in smem
};

__device__ __forceinline__ float2 ffma2f(float2 a, float2 b, float2 c) {
  union { float2 f; unsigned long long u; } ua, ub, uc;
  ua.f = a; ub.f = b; uc.f = c;
  asm("fma.rn.f32x2 %0, %1, %2, %0;" : "+l"(uc.u) : "l"(ua.u), "l"(ub.u));
  return uc.f;
}

__device__ __forceinline__ float fast_tanh(float x) {
  // tanh(x) = sign(x) * (1 - 2/(1 + e^{2|x|})), via ex2/rcp approx (~1e-6 abs err)
  float ax = fabsf(x);
  float e;
  asm("ex2.approx.f32 %0, %1;" : "=f"(e) : "f"(ax * 2.885390081777927f)); // 2*log2(e)
  float r;
  asm("rcp.approx.f32 %0, %1;" : "=f"(r) : "f"(e + 1.0f));
  float t = fmaf(-2.0f, r, 1.0f);
  return copysignf(t, x);
}

__global__ __launch_bounds__(256, 1)
void ode_tsit5_kernel(const float* __restrict__ ts, const float* __restrict__ y0,
                      const float* __restrict__ us, const float* __restrict__ W1,
                      const float* __restrict__ b1, const float* __restrict__ W2,
                      const float* __restrict__ b2, float* __restrict__ out,
                      int n_steps)
{
  extern __shared__ SmemLayout smem_raw[];
  SmemLayout& S = smem_raw[0];
  const int tid = threadIdx.x;
  const int b   = blockIdx.x;
  const float* usb = us + (size_t)b * N_K_STEPS * N_INPUT;

  // ---- one-time: W2 -> shared as float2 [k-pair][output]
  for (int idx = tid; idx < 128 * 128; idx += 256) {
    int p = idx >> 7, o = idx & 127;
    S.w2[idx] = make_float2(W2[o * 256 + 2 * p], W2[o * 256 + 2 * p + 1]);
  }
  // ---- one-time: ts -> shared
  for (int i = tid; i < n_steps; i += 256) S.tsh[i] = ts[i];

  // ---- one-time: this thread's W1 row -> registers as 41 float4
  float4 w1r[41];
  {
    const float* w1row = W1 + tid * FAN_IN;
    #pragma unroll
    for (int p = 0; p < 40; ++p)
      w1r[p] = make_float4(w1row[4*p], w1row[4*p+1], w1row[4*p+2], w1row[4*p+3]);
    w1r[40] = make_float4(w1row[160], 0.0f, 0.0f, 0.0f);
  }
  const float b1t = b1[tid];
  const float b2t = b2[tid & 127];

  float y_reg = 0.0f;
  if (tid < 128) {
    y_reg = y0[b * N_STATE + tid];
    out[(size_t)b * N_K_STEPS * N_STATE + tid] = y_reg;   // row 0 = y0
  }
  if (tid == 0) {
    float* zf = (float*)S.zs4;
    zf[161] = 0.0f; zf[162] = 0.0f; zf[163] = 0.0f;       // pad
  }
  __syncthreads();

  float* zsf = (float*)S.zs4;
  const float4* hs4 = (const float4*)S.hs;

  // stage-C work decomposition
  const int og = (tid & 31) * 4;   // 4 consecutive outputs
  const int ks = tid >> 5;         // k-slice 0..7 (32 k each)

  for (int s = 0; s < n_steps - 1; ++s) {
    const float t0 = S.tsh[s];
    const float t1 = S.tsh[s + 1];
    const float hstep = t1 - t0;

    // ---- step setup: Hermite-interpolated u for stages 1..5
    if (tid < 160) {
      int stg = (tid >> 5) + 1;        // 1..5
      int m   = tid & 31;
      float u0v = usb[s * N_INPUT + m];
      float u1v = usb[(s + 1) * N_INPUT + m];
      float hd1 = u1v - u0v;           // h * d[s+1] == u1 - u0 exactly
      float hd0;
      if (s == 0) {
        hd0 = hd1;
      } else {
        float um  = usb[(s - 1) * N_INPUT + m];
        float dtp = t0 - S.tsh[s - 1];
        hd0 = hstep * (u0v - um) / dtp;
      }
      float th = c_C[stg];
      float t2 = th * th, t3 = t2 * th;
      float c00 =  2.f * t3 - 3.f * t2 + 1.f;
      float c01 =        t3 - 2.f * t2 + th;
      float c10 = -2.f * t3 + 3.f * t2;
      float c11 =        t3 -       t2;
      S.ustg[stg][m] = c00 * u0v + c01 * hd0 + c10 * u1v + c11 * hd1;
    }

    #pragma unroll 1
    for (int st = 0; st < 6; ++st) {
      // ---- (A) assemble z = [t, ytmp, u(theta)] in shared
      if (st == 0) {
        if (tid < 128)       zsf[1 + tid] = y_reg;
        else if (tid < 160)  zsf[129 + (tid - 128)] = usb[s * N_INPUT + (tid - 128)];
        else if (tid == 160) zsf[0] = t0;
      } else {
        if (tid < 128) {
          float kprev = b2t;
          #pragma unroll
          for (int j = 0; j < 8; ++j) kprev += S.partial[j * 128 + tid];
          S.ksh[st - 1][tid] = kprev;
          float acc = c_A[st - 1][st - 1] * kprev;
          for (int j = 0; j < st - 1; ++j)
            acc += c_A[st - 1][j] * S.ksh[j][tid];
          zsf[1 + tid] = y_reg + hstep * acc;
        } else if (tid < 160) {
          zsf[129 + (tid - 128)] = S.ustg[st][tid - 128];
        } else if (tid == 160) {
          zsf[0] = t0 + c_C[st] * hstep;
        }
      }
      __syncthreads();

      // ---- (B) hidden layer: h[tid] = tanh(W1[tid,:] . z + b1[tid])
      {
        float2 a0 = make_float2(0.f, 0.f), a1 = a0, a2 = a0, a3 = a0;
        #pragma unroll
        for (int p = 0; p < 40; p += 2) {
          float4 zv = S.zs4[p];
          a0 = ffma2f(make_float2(w1r[p].x, w1r[p].y), make_float2(zv.x, zv.y), a0);
          a1 = ffma2f(make_float2(w1r[p].z, w1r[p].w), make_float2(zv.z, zv.w), a1);
          float4 zw = S.zs4[p + 1];
          a2 = ffma2f(make_float2(w1r[p+1].x, w1r[p+1].y), make_float2(zw.x, zw.y), a2);
          a3 = ffma2f(make_float2(w1r[p+1].z, w1r[p+1].w), make_float2(zw.z, zw.w), a3);
        }
        {
          float4 zv = S.zs4[40];
          a0 = ffma2f(make_float2(w1r[40].x, w1r[40].y), make_float2(zv.x, zv.y), a0);
        }
        float sum = (a0.x + a0.y) + (a1.x + a1.y) + (a2.x + a2.y) + (a3.x + a3.y) + b1t;
        S.hs[tid] = fast_tanh(sum);
      }
      __syncthreads();

      // ---- (C) output layer: 4 outputs per thread, 32 k (16 pairs) per thread
      {
        // preload this thread's h slice: 8 float4 broadcasts
        float4 h4[8];
        #pragma unroll
        for (int i = 0; i < 8; ++i) h4[i] = hs4[ks * 8 + i];

        float2 accA[4], accB[4];
        #pragma unroll
        for (int j = 0; j < 4; ++j) { accA[j] = make_float2(0.f, 0.f); accB[j] = make_float2(0.f, 0.f); }

        #pragma unroll
        for (int i = 0; i < 8; ++i) {
          const int p0 = ks * 16 + 2 * i;
          float2 h0 = make_float2(h4[i].x, h4[i].y);   // k-pair p0
          float2 h1 = make_float2(h4[i].z, h4[i].w);   // k-pair p0+1
          float4 wA0 = *(const float4*)&S.w2[p0 * 128 + og];           // (p0, og), (p0, og+1)
          float4 wA1 = *(const float4*)&S.w2[p0 * 128 + og + 2];       // (p0, og+2), (p0, og+3)
          float4 wB0 = *(const float4*)&S.w2[(p0 + 1) * 128 + og];
          float4 wB1 = *(const float4*)&S.w2[(p0 + 1) * 128 + og + 2];
          accA[0] = ffma2f(make_float2(wA0.x, wA0.y), h0, accA[0]);
          accA[1] = ffma2f(make_float2(wA0.z, wA0.w), h0, accA[1]);
          accA[2] = ffma2f(make_float2(wA1.x, wA1.y), h0, accA[2]);
          accA[3] = ffma2f(make_float2(wA1.z, wA1.w), h0, accA[3]);
          accB[0] = ffma2f(make_float2(wB0.x, wB0.y), h1, accB[0]);
          accB[1] = ffma2f(make_float2(wB0.z, wB0.w), h1, accB[1]);
          accB[2] = ffma2f(make_float2(wB1.x, wB1.y), h1, accB[2]);
          accB[3] = ffma2f(make_float2(wB1.z, wB1.w), h1, accB[3]);
        }
        float4 pv;
        pv.x = accA[0].x + accA[0].y + accB[0].x + accB[0].y;
        pv.y = accA[1].x + accA[1].y + accB[1].x + accB[1].y;
        pv.z = accA[2].x + accA[2].y + accB[2].x + accB[2].y;
        pv.w = accA[3].x + accA[3].y + accB[3].x + accB[3].y;
        *(float4*)&S.partial[ks * 128 + og] = pv;
      }
      __syncthreads();
    }

    // ---- final Runge-Kutta combine + output write
    if (tid < 128) {
      float k5 = b2t;
      #pragma unroll
      for (int j = 0; j < 8; ++j) k5 += S.partial[j * 128 + tid];
      float acc = c_B[5] * k5;
      #pragma unroll
      for (int j = 0; j < 5; ++j)
        acc += c_B[j] * S.ksh[j][tid];
      y_reg += hstep * acc;
      out[((size_t)b * N_K_STEPS + (s + 1)) * N_STATE + tid] = y_reg;
    }
    // next iteration's (A)-barrier provides ordering
  }
}

extern "C" void kernel_launch(void* const* d_in, const int* in_sizes, int n_in,
                              void* d_out, int out_size) {
  const float* ts = (const float*)d_in[0];
  const float* y0 = (const float*)d_in[1];
  const float* us = (const float*)d_in[2];
  const float* W1 = (const float*)d_in[3];
  const float* b1 = (const float*)d_in[4];
  const float* W2 = (const float*)d_in[5];
  const float* b2 = (const float*)d_in[6];
  float* out = (float*)d_out;

  const int n_steps = in_sizes[0];             // 512
  const int batch   = in_sizes[1] / N_STATE;   // 64

  const size_t smem_bytes = sizeof(SmemLayout);
  cudaFuncSetAttribute(ode_tsit5_kernel,
                       cudaFuncAttributeMaxDynamicSharedMemorySize, (int)smem_bytes);
  ode_tsit5_kernel<<<batch, 256, smem_bytes>>>(ts, y0, us, W1, b1, W2, b2, out, n_steps);
}